// round 16
// baseline (speedup 1.0000x reference)
#include <cuda_runtime.h>
#include <cuda_bf16.h>
#include <cuda_fp8.h>
#include <math.h>
#include <stdint.h>

// ---------------- model constants ----------------
#define LNUM 6
#define DMODEL 1024
#define NH 16
#define NKV 4
#define HDIM 64
#define BATCH 2
#define SEQ 2048
#define TT (BATCH*SEQ)          // 4096 tokens
#define VSZ 50257
#define HSZ 4096
#define MLPD 3072
#define QKVD 1536               // 1024 + 256 + 256
#define EPSF 1.1920929e-07f
#define WSC 64.f                // fp8 weight pre-scale
#define WSCI (1.f/64.f)

typedef __nv_bfloat16 bf16;
typedef __nv_bfloat162 bf162;

// ---------------- scratch (device globals; no allocation allowed) ----------------
__device__ float   g_X[TT*DMODEL];
__device__ float   g_X0[TT*DMODEL];
__device__ float   g_SK[LNUM*TT*DMODEL];
__device__ float   g_COS[SEQ*32];
__device__ float   g_SIN[SEQ*32];
__device__ float   g_SUMEXP[TT];
__device__ float   g_TGT[TT];
__device__ bf16    g_XRh[TT*DMODEL];      // bf16 rmsnorm out (Wf input, tgt input)
__device__ uint8_t g_XR8[TT*DMODEL];      // fp8 rmsnorm out (QKV + loss input)
__device__ bf16    g_QKVh[TT*QKVD];       // QKV GEMM out (bf16)
__device__ uint8_t g_ATT8[TT*DMODEL];     // attention out fp8 (Wo input)
__device__ uint8_t g_MH8[TT*MLPD];        // MLP hidden fp8 (Wo2 input)
__device__ bf16    g_Qh[TT*NH*HDIM];
__device__ bf16    g_Kh[TT*NKV*HDIM];
__device__ bf16    g_Vh[TT*NKV*HDIM];
__device__ uint8_t g_WQKV8[(size_t)LNUM*QKVD*DMODEL];
__device__ uint8_t g_WO8[(size_t)LNUM*DMODEL*DMODEL];
__device__ bf16    g_WFh[(size_t)LNUM*MLPD*DMODEL];
__device__ uint8_t g_WO28[(size_t)LNUM*DMODEL*MLPD];
__device__ uint8_t g_UE8[(size_t)VSZ*512];

// ---------------- helpers ----------------
__device__ __forceinline__ float block_sum_256(float v) {
    __shared__ float sh[8];
    #pragma unroll
    for (int o = 16; o; o >>= 1) v += __shfl_xor_sync(0xffffffffu, v, o);
    if ((threadIdx.x & 31) == 0) sh[threadIdx.x >> 5] = v;
    __syncthreads();
    if (threadIdx.x == 0) {
        float s = 0.f;
        #pragma unroll
        for (int i = 0; i < 8; i++) s += sh[i];
        sh[0] = s;
    }
    __syncthreads();
    return sh[0];
}

__device__ __forceinline__ void mma_bf16(float* c, uint32_t a0, uint32_t a1,
                                         uint32_t a2, uint32_t a3,
                                         uint32_t b0, uint32_t b1) {
    asm volatile(
        "mma.sync.aligned.m16n8k16.row.col.f32.bf16.bf16.f32 "
        "{%0,%1,%2,%3}, {%4,%5,%6,%7}, {%8,%9}, {%0,%1,%2,%3};"
        : "+f"(c[0]), "+f"(c[1]), "+f"(c[2]), "+f"(c[3])
        : "r"(a0), "r"(a1), "r"(a2), "r"(a3), "r"(b0), "r"(b1));
}
__device__ __forceinline__ void mma_fp8(float* c, uint32_t a0, uint32_t a1,
                                        uint32_t a2, uint32_t a3,
                                        uint32_t b0, uint32_t b1) {
    asm volatile(
        "mma.sync.aligned.m16n8k32.row.col.f32.e4m3.e4m3.f32 "
        "{%0,%1,%2,%3}, {%4,%5,%6,%7}, {%8,%9}, {%0,%1,%2,%3};"
        : "+f"(c[0]), "+f"(c[1]), "+f"(c[2]), "+f"(c[3])
        : "r"(a0), "r"(a1), "r"(a2), "r"(a3), "r"(b0), "r"(b1));
}

__device__ __forceinline__ uint4 ldsm4(uint32_t addr) {
    uint4 r;
    asm volatile("ldmatrix.sync.aligned.m8n8.x4.shared.b16 {%0,%1,%2,%3}, [%4];"
        : "=r"(r.x), "=r"(r.y), "=r"(r.z), "=r"(r.w) : "r"(addr));
    return r;
}
__device__ __forceinline__ uint4 ldsm4t(uint32_t addr) {
    uint4 r;
    asm volatile("ldmatrix.sync.aligned.m8n8.x4.trans.shared.b16 {%0,%1,%2,%3}, [%4];"
        : "=r"(r.x), "=r"(r.y), "=r"(r.z), "=r"(r.w) : "r"(addr));
    return r;
}
__device__ __forceinline__ uint32_t packbf(float x, float y) {
    bf162 r = __floats2bfloat162_rn(x, y);
    return *(uint32_t*)&r;
}
__device__ __forceinline__ uint16_t f2e4m3x2(float x, float y) {
    __nv_fp8x2_storage_t r = __nv_cvt_float2_to_fp8x2(make_float2(x, y),
                                                      __NV_SATFINITE, __NV_E4M3);
    return (uint16_t)r;
}
__device__ __forceinline__ uint8_t f2e4m3(float x) {
    return (uint8_t)__nv_cvt_float_to_fp8(x, __NV_SATFINITE, __NV_E4M3);
}

#define CP16(dst, src) asm volatile("cp.async.cg.shared.global [%0], [%1], 16;" :: "r"(dst), "l"(src))
#define CP_COMMIT()    asm volatile("cp.async.commit_group;")
#define CP_WAIT1()     asm volatile("cp.async.wait_group 1;")

// ---------------- rope tables ----------------
__global__ void rope_table_kernel(float* __restrict__ cosT, float* __restrict__ sinT) {
    int idx = blockIdx.x * 256 + threadIdx.x;
    if (idx >= SEQ * 32) return;
    int t = idx >> 5, j = idx & 31;
    double f = pow(10000.0, -(double)j / 32.0);
    double a = (double)t * f;
    cosT[idx] = (float)cos(a);
    sinT[idx] = (float)sin(a);
}

// ---------------- weight converts: Wf->bf16, Wo/Wo2/UE->fp8*64 ----------------
__global__ void wconv_kernel(const float4* __restrict__ s1, bf162* __restrict__ d1, int n1,
                             const float4* __restrict__ s2, uint32_t* __restrict__ d2, int n2,
                             const float4* __restrict__ s3, uint32_t* __restrict__ d3, int n3,
                             const float4* __restrict__ s4, uint32_t* __restrict__ d4, int n4) {
    long i = (long)blockIdx.x * 256 + threadIdx.x;
    if (i < n1) {
        float4 v = s1[i];
        d1[2 * i]     = __floats2bfloat162_rn(v.x, v.y);
        d1[2 * i + 1] = __floats2bfloat162_rn(v.z, v.w);
        return;
    }
    i -= n1;
    const float4* s; uint32_t* d;
    if (i < n2) { s = s2; d = d2; }
    else { i -= n2;
        if (i < n3) { s = s3; d = d3; }
        else { i -= n3; if (i >= n4) return; s = s4; d = d4; } }
    float4 v = s[i];
    uint32_t lo = f2e4m3x2(v.x * WSC, v.y * WSC);
    uint32_t hi = f2e4m3x2(v.z * WSC, v.w * WSC);
    d[i] = lo | (hi << 16);
}

// ---------------- pack Wq/Wk/Wv -> fp8*64 WQKV[l][1536][1024] ----------------
__global__ void pack_qkv_kernel(const float* __restrict__ Wq, const float* __restrict__ Wk,
                                const float* __restrict__ Wv, uint32_t* __restrict__ out) {
    const int ROWF4 = DMODEL / 4;
    const int TOT = LNUM * QKVD * ROWF4;
    int i = blockIdx.x * 256 + threadIdx.x;
    if (i >= TOT) return;
    int rowg = i / ROWF4, c = i % ROWF4;
    int l = rowg / QKVD, r = rowg % QKVD;
    const float4* src;
    if (r < 1024)      src = (const float4*)(Wq + ((size_t)l * 1024 + r) * DMODEL);
    else if (r < 1280) src = (const float4*)(Wk + ((size_t)l * 256 + (r - 1024)) * DMODEL);
    else               src = (const float4*)(Wv + ((size_t)l * 256 + (r - 1280)) * DMODEL);
    float4 v = src[c];
    uint32_t lo = f2e4m3x2(v.x * WSC, v.y * WSC);
    uint32_t hi = f2e4m3x2(v.z * WSC, v.w * WSC);
    out[i] = lo | (hi << 16);
}

// ---------------- embedding + rmsnorm ----------------
__global__ void embed_kernel(const int* __restrict__ ids, const float* __restrict__ u_emb,
                             const float* __restrict__ b_emb,
                             float* __restrict__ X, float* __restrict__ X0) {
    int t = blockIdx.x;
    int s = t & (SEQ - 1);
    int id = ids[t];
    int pi = (s == 0) ? 0 : ids[t - 1];
    int bi = ((pi % HSZ) * (VSZ % HSZ) % HSZ + id % HSZ) % HSZ;
    int tid = threadIdx.x;
    float v[4];
    float ssq = 0.f;
    #pragma unroll
    for (int i = 0; i < 4; i++) {
        int d = i * 256 + tid;
        float x = (d < 512) ? u_emb[(size_t)id * 512 + d] : b_emb[(size_t)bi * 512 + (d - 512)];
        v[i] = x; ssq += x * x;
    }
    float tot = block_sum_256(ssq);
    float r = rsqrtf(tot * (1.f / DMODEL) + EPSF);
    #pragma unroll
    for (int i = 0; i < 4; i++) {
        int d = i * 256 + tid;
        float o = v[i] * r;
        X[(size_t)t * DMODEL + d] = o;
        X0[(size_t)t * DMODEL + d] = o;
    }
}

// ---------------- residual mix (+optional skip) then rmsnorm -> fp8 ----------------
__global__ void mix_rmsn_kernel(float* __restrict__ X, const float* __restrict__ X0,
                                uint8_t* __restrict__ XR8, const float* __restrict__ rm,
                                const float* __restrict__ skip, const float* __restrict__ sw) {
    int t = blockIdx.x, tid = threadIdx.x;
    float v[4]; float ssq = 0.f;
    #pragma unroll
    for (int i = 0; i < 4; i++) {
        int d = i * 256 + tid;
        size_t off = (size_t)t * DMODEL + d;
        float x = X[off];
        if (skip) x += sw[d] * skip[off];
        x = rm[d] * x + rm[DMODEL + d] * X0[off];
        v[i] = x; ssq += x * x;
    }
    float tot = block_sum_256(ssq);
    float r = rsqrtf(tot * (1.f / DMODEL) + EPSF);
    #pragma unroll
    for (int i = 0; i < 4; i++) {
        int d = i * 256 + tid;
        size_t off = (size_t)t * DMODEL + d;
        X[off] = v[i];
        XR8[off] = f2e4m3(v[i] * r);
    }
}

// ---------------- plain rmsnorm -> bf16 (+optional fp8) ----------------
__global__ void rmsn_kernel(const float* __restrict__ X, bf16* __restrict__ XR,
                            uint8_t* __restrict__ XR8) {
    int t = blockIdx.x, tid = threadIdx.x;
    float v[4]; float ssq = 0.f;
    #pragma unroll
    for (int i = 0; i < 4; i++) {
        int d = i * 256 + tid;
        v[i] = X[(size_t)t * DMODEL + d];
        ssq += v[i] * v[i];
    }
    float tot = block_sum_256(ssq);
    float r = rsqrtf(tot * (1.f / DMODEL) + EPSF);
    #pragma unroll
    for (int i = 0; i < 4; i++) {
        int d = i * 256 + tid;
        size_t off = (size_t)t * DMODEL + d;
        XR[off] = __float2bfloat16(v[i] * r);
        if (XR8) XR8[off] = f2e4m3(v[i] * r);
    }
}

// ---------------- per-head rmsnorm + rope, bf16 QKV -> bf16 Qh/Kh/Vh ----------------
__device__ __forceinline__ void rope_norm_store(const bf16* __restrict__ src,
                                                bf16* __restrict__ dst, int t, int lane,
                                                float gain,
                                                const float* __restrict__ cosT,
                                                const float* __restrict__ sinT) {
    int s = t & (SEQ - 1);
    float v1 = __bfloat162float(src[lane]), v2 = __bfloat162float(src[lane + 32]);
    float ssq = v1 * v1 + v2 * v2;
    #pragma unroll
    for (int off = 16; off; off >>= 1) ssq += __shfl_xor_sync(0xffffffffu, ssq, off);
    float r = rsqrtf(ssq * (1.f / HDIM) + EPSF);
    v1 *= r; v2 *= r;
    float c = cosT[s * 32 + lane], sn = sinT[s * 32 + lane];
    dst[lane]      = __float2bfloat16((v1 * c + v2 * sn) * gain);
    dst[lane + 32] = __float2bfloat16((-v1 * sn + v2 * c) * gain);
}

__global__ void qkrope_kernel(const bf16* __restrict__ QKV,
                              bf16* __restrict__ Qh, bf16* __restrict__ Kh, bf16* __restrict__ Vh,
                              const float* __restrict__ cosT, const float* __restrict__ sinT,
                              const float* __restrict__ qg) {
    int gw = blockIdx.x * 8 + (threadIdx.x >> 5);
    int lane = threadIdx.x & 31;
    const int NQ = TT * NH, NK = TT * NKV;
    if (gw < NQ) {
        int t = gw >> 4, h = gw & 15;
        rope_norm_store(QKV + (size_t)t * QKVD + h * HDIM,
                        Qh + (size_t)t * (NH * HDIM) + h * HDIM,
                        t, lane, qg[h] * 0.125f, cosT, sinT);
    } else if (gw < NQ + NK) {
        int g2 = gw - NQ;
        int t = g2 >> 2, h = g2 & 3;
        rope_norm_store(QKV + (size_t)t * QKVD + 1024 + h * HDIM,
                        Kh + (size_t)t * (NKV * HDIM) + h * HDIM,
                        t, lane, 1.f, cosT, sinT);
    } else {
        int g3 = gw - NQ - NK;
        if (g3 >= TT * NKV) return;
        int t = g3 >> 2, h = g3 & 3;
        const bf16* src = QKV + (size_t)t * QKVD + 1280 + h * HDIM;
        bf16* dst = Vh + (size_t)t * (NKV * HDIM) + h * HDIM;
        dst[lane]      = src[lane];
        dst[lane + 32] = src[lane + 32];
    }
}

// ======== shared GEMM geometry: 128x128 tile, 8 warps (32x64), 3-stage cp.async ========
// smem row = 64 data bytes + 16 pad = 80 bytes; per-stage buffer = 128*80 = 10240 B.
#define ROWB 80
#define BUFB (128*ROWB)
#define GEMM_SMEM (6*BUFB)      // 3 stages x (A+B) = 61440 bytes

// ---------------- BF16 GEMM (Wf only): C8 = fp8(relu(acc)^2) ----------------
__global__ void __launch_bounds__(256) gemm_bf16_kernel(
    const bf16* __restrict__ A, int lda, const bf16* __restrict__ W,
    uint8_t* __restrict__ C8, int ldc, int M, int N, int K)
{
    extern __shared__ __align__(16) uint8_t dynsm[];
    uint32_t sA = (uint32_t)__cvta_generic_to_shared(dynsm);
    uint32_t sB = sA + 3 * BUFB;

    int tid = threadIdx.x;
    int lane = tid & 31, wid = tid >> 5;
    int wm = wid & 3, wn = wid >> 2;
    int m0 = blockIdx.y * 128, n0 = blockIdx.x * 128;

    int arow = tid >> 1;
    int acB = (tid & 1) * 32;                       // byte offset in 64B k-row
    const bf16* ApA = A + (size_t)(m0 + arow) * lda + acB / 2;
    int wrow = n0 + arow;
    int wsafe = (wrow < N) ? wrow : (N - 1);
    const bf16* ApW = W + (size_t)wsafe * K + acB / 2;
    uint32_t dA = sA + (uint32_t)(arow * ROWB + acB);
    uint32_t dB = sB + (uint32_t)(arow * ROWB + acB);

    int tIdx = lane >> 3, rIn = lane & 7;
    int aRow = wm * 32 + (tIdx & 1) * 8 + rIn;
    int kColB = (tIdx >> 1) * 16;
    uint32_t aOff[2][2], bOff[4][2];
    #pragma unroll
    for (int i = 0; i < 2; i++)
        #pragma unroll
        for (int s = 0; s < 2; s++)
            aOff[i][s] = (uint32_t)((aRow + i * 16) * ROWB + kColB + s * 32);
    #pragma unroll
    for (int jj = 0; jj < 4; jj++)
        #pragma unroll
        for (int s = 0; s < 2; s++)
            bOff[jj][s] = (uint32_t)((wn * 64 + jj * 16 + (tIdx & 1) * 8 + rIn) * ROWB + kColB + s * 32);

    float acc[2][8][4];
    #pragma unroll
    for (int i = 0; i < 2; i++)
        #pragma unroll
        for (int j = 0; j < 8; j++)
            #pragma unroll
            for (int c = 0; c < 4; c++) acc[i][j][c] = 0.f;

    int nk = K >> 5;   // 32 bf16 = 64 bytes per tile
    {
        CP16(dA, ApA); CP16(dA + 16, ApA + 8);
        CP16(dB, ApW); CP16(dB + 16, ApW + 8);
        CP_COMMIT();
        if (nk > 1) {
            CP16(dA + BUFB, ApA + 32); CP16(dA + BUFB + 16, ApA + 40);
            CP16(dB + BUFB, ApW + 32); CP16(dB + BUFB + 16, ApW + 40);
        }
        CP_COMMIT();
    }
    int b0 = 0, b1 = 1, b2 = 2;
    for (int kt = 0; kt < nk; kt++) {
        CP_WAIT1();
        __syncthreads();
        if (kt + 2 < nk) {
            int k0 = (kt + 2) << 5;
            uint32_t bo = (uint32_t)b2 * BUFB;
            CP16(dA + bo, ApA + k0); CP16(dA + bo + 16, ApA + k0 + 8);
            CP16(dB + bo, ApW + k0); CP16(dB + bo + 16, ApW + k0 + 8);
        }
        CP_COMMIT();

        uint32_t bA = sA + (uint32_t)b0 * BUFB;
        uint32_t bB = sB + (uint32_t)b0 * BUFB;
        #pragma unroll
        for (int s = 0; s < 2; s++) {
            uint4 af0 = ldsm4(bA + aOff[0][s]);
            uint4 af1 = ldsm4(bA + aOff[1][s]);
            #pragma unroll
            for (int jj = 0; jj < 4; jj++) {
                uint4 bfr = ldsm4(bB + bOff[jj][s]);
                mma_bf16(acc[0][2 * jj],     af0.x, af0.y, af0.z, af0.w, bfr.x, bfr.z);
                mma_bf16(acc[0][2 * jj + 1], af0.x, af0.y, af0.z, af0.w, bfr.y, bfr.w);
                mma_bf16(acc[1][2 * jj],     af1.x, af1.y, af1.z, af1.w, bfr.x, bfr.z);
                mma_bf16(acc[1][2 * jj + 1], af1.x, af1.y, af1.z, af1.w, bfr.y, bfr.w);
            }
        }
        int t = b0; b0 = b1; b1 = b2; b2 = t;
    }

    int r0 = lane >> 2, c0v = (lane & 3) * 2;
    #pragma unroll
    for (int i = 0; i < 2; i++) {
        int mrow = m0 + (2 * wm + i) * 16 + r0;
        #pragma unroll
        for (int j = 0; j < 8; j++) {
            int col = n0 + (8 * wn + j) * 8 + c0v;
            uint8_t* p0 = C8 + (size_t)mrow * ldc + col;
            uint8_t* p1 = p0 + (size_t)8 * ldc;
            float a = fmaxf(acc[i][j][0], 0.f), b = fmaxf(acc[i][j][1], 0.f);
            float c = fmaxf(acc[i][j][2], 0.f), d = fmaxf(acc[i][j][3], 0.f);
            *(uint16_t*)p0 = f2e4m3x2(a * a, b * b);
            *(uint16_t*)p1 = f2e4m3x2(c * c, d * d);
        }
    }
}

// ---------------- FP8 GEMM: C[M,N] = (A8 @ W8^T) * cmul ----------------
// mode 0: Ch = bf16(acc)       mode 1: Cf += scale[n]*acc (in-place; also -> Csk)
// mode 3: atomicAdd(sumexp[m], sum_n exp(30*tanh(acc/30)))
__global__ void __launch_bounds__(256) gemm_fp8_kernel(
    const uint8_t* __restrict__ A, int lda, const uint8_t* __restrict__ W,
    float* __restrict__ Cf, bf16* __restrict__ Ch, float* __restrict__ Csk, int ldc,
    const float* __restrict__ scale, float* __restrict__ sumexp,
    int M, int N, int K, int mode, float cmul)
{
    extern __shared__ __align__(16) uint8_t dynsm[];
    uint32_t sA = (uint32_t)__cvta_generic_to_shared(dynsm);
    uint32_t sB = sA + 3 * BUFB;

    int tid = threadIdx.x;
    int lane = tid & 31, wid = tid >> 5;
    int wm = wid & 3, wn = wid >> 2;
    int m0 = blockIdx.y * 128, n0 = blockIdx.x * 128;

    int arow = tid >> 1;
    int acB = (tid & 1) * 32;
    const uint8_t* ApA = A + (size_t)(m0 + arow) * lda + acB;
    int wrow = n0 + arow;
    int wsafe = (wrow < N) ? wrow : (N - 1);
    const uint8_t* ApW = W + (size_t)wsafe * K + acB;
    uint32_t dA = sA + (uint32_t)(arow * ROWB + acB);
    uint32_t dB = sB + (uint32_t)(arow * ROWB + acB);

    int tIdx = lane >> 3, rIn = lane & 7;
    int aRow = wm * 32 + (tIdx & 1) * 8 + rIn;
    int kColB = (tIdx >> 1) * 16;
    uint32_t aOff[2][2], bOff[4][2];
    #pragma unroll
    for (int i = 0; i < 2; i++)
        #pragma unroll
        for (int s = 0; s < 2; s++)
            aOff[i][s] = (uint32_t)((aRow + i * 16) * ROWB + kColB + s * 32);
    #pragma unroll
    for (int jj = 0; jj < 4; jj++)
        #pragma unroll
        for (int s = 0; s < 2; s++)
            bOff[jj][s] = (uint32_t)((wn * 64 + jj * 16 + (tIdx & 1) * 8 + rIn) * ROWB + kColB + s * 32);

    float acc[2][8][4];
    #pragma unroll
    for (int i = 0; i < 2; i++)
        #pragma unroll
        for (int j = 0; j < 8; j++)
            #pragma unroll
            for (int c = 0; c < 4; c++) acc[i][j][c] = 0.f;

    int nk = K >> 6;   // 64 fp8 = 64 bytes per tile
    {
        CP16(dA, ApA); CP16(dA + 16, ApA + 16);
        CP16(dB, ApW); CP16(dB + 16, ApW + 16);
        CP_COMMIT();
        if (nk > 1) {
            CP16(dA + BUFB, ApA + 64); CP16(dA + BUFB + 16, ApA + 80);
            CP16(dB + BUFB, ApW + 64); CP16(dB + BUFB + 16, ApW + 80);
        }
        CP_COMMIT();
    }
    int b0 = 0, b1 = 1, b2 = 2;
    for (int kt = 0; kt < nk; kt++) {
        CP_WAIT1();
        __syncthreads();
        if (kt + 2 < nk) {
            int k0 = (kt + 2) << 6;
            uint32_t bo = (uint32_t)b2 * BUFB;
            CP16(dA + bo, ApA + k0); CP16(dA + bo + 16, ApA + k0 + 16);
            CP16(dB + bo, ApW + k0); CP16(dB + bo + 16, ApW + k0 + 16);
        }
        CP_COMMIT();

        uint32_t bA = sA + (uint32_t)b0 * BUFB;
        uint32_t bB = sB + (uint32_t)b0 * BUFB;
        #pragma unroll
        for (int s = 0; s < 2; s++) {
            uint4 af0 = ldsm4(bA + aOff[0][s]);
            uint4 af1 = ldsm4(bA + aOff[1][s]);
            #pragma unroll
            for (int jj = 0; jj < 4; jj++) {
                uint4 bfr = ldsm4(bB + bOff[jj][s]);
                mma_fp8(acc[0][2 * jj],     af0.x, af0.y, af0.z, af0.w, bfr.x, bfr.z);
                mma_fp8(acc[0][2 * jj + 1], af0.x, af0.y, af0.z, af0.w, bfr.y, bfr.w);
                mma_fp8(acc[1][2 * jj],     af1.x, af1.y, af1.z, af1.w, bfr.x, bfr.z);
                mma_fp8(acc[1][2 * jj + 1], af1.x, af1.y, af1.z, af1.w, bfr.y, bfr.w);
            }
        }
        int t = b0; b0 = b1; b1 = b2; b2 = t;
    }

    #pragma unroll
    for (int i = 0; i < 2; i++)
        #pragma unroll
        for (int j = 0; j < 8; j++)
            #pragma unroll
            for (int c = 0; c < 4; c++) acc[i][j][c] *= cmul;

    int r0 = lane >> 2, c0v = (lane & 3) * 2;

    if (mode == 3) {
        #pragma unroll
        for (int i = 0; i < 2; i++) {
            #pragma unroll
            for (int h = 0; h < 2; h++) {
                float s = 0.f;
                #pragma unroll
                for (int j = 0; j < 8; j++) {
                    int col = n0 + (8 * wn + j) * 8 + c0v;
                    if (col < N)     s += __expf(30.f * tanhf(acc[i][j][h * 2 + 0] * (1.f / 30.f)));
                    if (col + 1 < N) s += __expf(30.f * tanhf(acc[i][j][h * 2 + 1] * (1.f / 30.f)));
                }
                s += __shfl_xor_sync(0xffffffffu, s, 1);
                s += __shfl_xor_sync(0xffffffffu, s, 2);
                if ((lane & 3) == 0) {
                    int row = m0 + (2 * wm + i) * 16 + r0 + h * 8;
                    atomicAdd(&sumexp[row], s);
                }
            }
        }
        return;
    }

    #pragma unroll
    for (int i = 0; i < 2; i++) {
        int mrow = m0 + (2 * wm + i) * 16 + r0;
        #pragma unroll
        for (int j = 0; j < 8; j++) {
            int col = n0 + (8 * wn + j) * 8 + c0v;
            if (mode == 0) {
                bf16* p0 = Ch + (size_t)mrow * ldc + col;
                bf16* p1 = p0 + (size_t)8 * ldc;
                *(bf162*)p0 = __floats2bfloat162_rn(acc[i][j][0], acc[i][j][1]);
                *(bf162*)p1 = __floats2bfloat162_rn(acc[i][j][2], acc[i][j][3]);
            } else { // mode 1
                float* p0 = Cf + (size_t)mrow * ldc + col;
                float* p1 = p0 + (size_t)8 * ldc;
                float2 sc = *(const float2*)(scale + col);
                float2 v0 = *(const float2*)p0;
                float2 v1 = *(const float2*)p1;
                v0.x += sc.x * acc[i][j][0]; v0.y += sc.y * acc[i][j][1];
                v1.x += sc.x * acc[i][j][2]; v1.y += sc.y * acc[i][j][3];
                *(float2*)p0 = v0; *(float2*)p1 = v1;
                if (Csk) {
                    float* q0 = Csk + (size_t)mrow * ldc + col;
                    float* q1 = q0 + (size_t)8 * ldc;
                    *(float2*)q0 = v0; *(float2*)q1 = v1;
                }
            }
        }
    }
}

// ---------------- BF16 MMA causal flash attention (GQA) -> fp8 out ----------------
#define FST 72   // halves per smem row
__global__ void __launch_bounds__(128) flash_mma_kernel(
    const bf16* __restrict__ Qh, const bf16* __restrict__ Kh,
    const bf16* __restrict__ Vh, uint8_t* __restrict__ O8)
{
    __shared__ __align__(16) bf16 Qs[64 * FST];
    __shared__ __align__(16) bf16 Ks[2][64 * FST];
    __shared__ __align__(16) bf16 Vs[2][64 * FST];

    int qt = blockIdx.x, bh = blockIdx.y;
    int b = bh >> 4, head = bh & 15, kvh = head >> 2;
    int tid = threadIdx.x, lane = tid & 31, wid = tid >> 5;
    int t0 = b * SEQ + qt * 64;

    #pragma unroll
    for (int i = 0; i < 4; i++) {
        int c = tid + i * 128;
        int r = c >> 3, off = (c & 7) * 8;
        *(uint4*)&Qs[r * FST + off] =
            *(const uint4*)(Qh + (size_t)(t0 + r) * (NH * HDIM) + head * HDIM + off);
    }
    __syncthreads();

    int tIdx = lane >> 3, rIn = lane & 7;
    uint32_t sQ = (uint32_t)__cvta_generic_to_shared(Qs);
    uint32_t sK = (uint32_t)__cvta_generic_to_shared(Ks);
    uint32_t sV = (uint32_t)__cvta_generic_to_shared(Vs);

    int qRow = wid * 16 + (tIdx & 1) * 8 + rIn;
    int qCol = (tIdx >> 1) * 8;
    uint4 aQ[4];
    #pragma unroll
    for (int c = 0; c < 4; c++)
        aQ[c] = ldsm4(sQ + (uint32_t)(qRow * FST + qCol + c * 16) * 2);

    float accO[8][4];
    #pragma unroll
    for (int j = 0; j < 8; j++)
        #pragma unroll
        for (int c = 0; c < 4; c++) accO[j][c] = 0.f;
    float m0 = -1e30f, m1 = -1e30f, l0 = 0.f, l1 = 0.f;

    int nkt = qt + 1;
    {
        int k0 = b * SEQ;
        #pragma unroll
        for (int i = 0; i < 4; i++) {
            int c = tid + i * 128;
            int r = c >> 3, off = (c & 7) * 8;
            uint32_t dd = (uint32_t)(r * FST + off) * 2;
            CP16(sK + dd, Kh + (size_t)(k0 + r) * (NKV * HDIM) + kvh * HDIM + off);
            CP16(sV + dd, Vh + (size_t)(k0 + r) * (NKV * HDIM) + kvh * HDIM + off);
        }
        CP_COMMIT();
    }
    int buf = 0;
    for (int kt = 0; kt < nkt; kt++) {
        if (kt + 1 < nkt) {
            int k0 = b * SEQ + (kt + 1) * 64;
            uint32_t bo = (uint32_t)((buf ^ 1) * 64 * FST) * 2;
            #pragma unroll
            for (int i = 0; i < 4; i++) {
                int c = tid + i * 128;
                int r = c >> 3, off = (c & 7) * 8;
                uint32_t dd = bo + (uint32_t)(r * FST + off) * 2;
                CP16(sK + dd, Kh + (size_t)(k0 + r) * (NKV * HDIM) + kvh * HDIM + off);
                CP16(sV + dd, Vh + (size_t)(k0 + r) * (NKV * HDIM) + kvh * HDIM + off);
            }
        }
        CP_COMMIT();
        CP_WAIT1();
        __syncthreads();

        uint32_t bK = sK + (uint32_t)(buf * 64 * FST) * 2;
        uint32_t bV = sV + (uint32_t)(buf * 64 * FST) * 2;

        float accS[8][4];
        #pragma unroll
        for (int j = 0; j < 8; j++)
            #pragma unroll
            for (int c = 0; c < 4; c++) accS[j][c] = 0.f;
        #pragma unroll
        for (int g = 0; g < 4; g++) {
            #pragma unroll
            for (int c = 0; c < 4; c++) {
                uint4 bfr = ldsm4(bK + (uint32_t)((g * 16 + (tIdx & 1) * 8 + rIn) * FST
                                                  + (tIdx >> 1) * 8 + c * 16) * 2);
                mma_bf16(accS[2 * g],     aQ[c].x, aQ[c].y, aQ[c].z, aQ[c].w, bfr.x, bfr.z);
                mma_bf16(accS[2 * g + 1], aQ[c].x, aQ[c].y, aQ[c].z, aQ[c].w, bfr.y, bfr.w);
            }
        }

        int r0 = lane >> 2, cbm = (lane & 3) * 2;
        if (kt == qt) {
            int qg0 = wid * 16 + r0;
            #pragma unroll
            for (int j = 0; j < 8; j++) {
                int kg = j * 8 + cbm;
                if (kg > qg0)         accS[j][0] = -1e30f;
                if (kg + 1 > qg0)     accS[j][1] = -1e30f;
                if (kg > qg0 + 8)     accS[j][2] = -1e30f;
                if (kg + 1 > qg0 + 8) accS[j][3] = -1e30f;
            }
        }

        float mx0 = -1e30f, mx1 = -1e30f;
        #pragma unroll
        for (int j = 0; j < 8; j++) {
            mx0 = fmaxf(mx0, fmaxf(accS[j][0], accS[j][1]));
            mx1 = fmaxf(mx1, fmaxf(accS[j][2], accS[j][3]));
        }
        mx0 = fmaxf(mx0, __shfl_xor_sync(0xffffffffu, mx0, 1));
        mx0 = fmaxf(mx0, __shfl_xor_sync(0xffffffffu, mx0, 2));
        mx1 = fmaxf(mx1, __shfl_xor_sync(0xffffffffu, mx1, 1));
        mx1 = fmaxf(mx1, __shfl_xor_sync(0xffffffffu, mx1, 2));
        float mn0 = fmaxf(m0, mx0), mn1 = fmaxf(m1, mx1);
        float al0 = __expf(m0 - mn0), al1 = __expf(m1 - mn1);
        m0 = mn0; m1 = mn1;
        float rs0 = 0.f, rs1 = 0.f;
        #pragma unroll
        for (int j = 0; j < 8; j++) {
            accS[j][0] = __expf(accS[j][0] - mn0);
            accS[j][1] = __expf(accS[j][1] - mn0);
            accS[j][2] = __expf(accS[j][2] - mn1);
            accS[j][3] = __expf(accS[j][3] - mn1);
            rs0 += accS[j][0] + accS[j][1];
            rs1 += accS[j][2] + accS[j][3];
        }
        rs0 += __shfl_xor_sync(0xffffffffu, rs0, 1);
        rs0 += __shfl_xor_sync(0xffffffffu, rs0, 2);
        rs1 += __shfl_xor_sync(0xffffffffu, rs1, 1);
        rs1 += __shfl_xor_sync(0xffffffffu, rs1, 2);
        l0 = l0 * al0 + rs0;
        l1 = l1 * al1 + rs1;
        #pragma unroll
        for (int j = 0; j < 8; j++) {
            accO[j][0] *= al0; accO[j][1] *= al0;
            accO[j][2] *= al1; accO[j][3] *= al1;
        }

        #pragma unroll
        for (int c = 0; c < 4; c++) {
            uint32_t a0 = packbf(accS[2 * c][0],     accS[2 * c][1]);
            uint32_t a1 = packbf(accS[2 * c][2],     accS[2 * c][3]);
            uint32_t a2 = packbf(accS[2 * c + 1][0], accS[2 * c + 1][1]);
            uint32_t a3 = packbf(accS[2 * c + 1][2], accS[2 * c + 1][3]);
            #pragma unroll
            for (int dg = 0; dg < 4; dg++) {
                uint4 bt = ldsm4t(bV + (uint32_t)((c * 16 + ((lane >> 3) & 1) * 8 + (lane & 7)) * FST
                                                  + dg * 16 + (lane >> 4) * 8) * 2);
                mma_bf16(accO[2 * dg],     a0, a1, a2, a3, bt.x, bt.y);
                mma_bf16(accO[2 * dg + 1], a0, a1, a2, a3, bt.z, bt.w);
            }
        }
        __syncthreads();
        buf ^= 1;
    }

    float li0 = 1.f / l0, li1 = 1.f / l1;
    int r0 = lane >> 2, cbm = (lane & 3) * 2;
    int row0 = t0 + wid * 16 + r0;
    #pragma unroll
    for (int j = 0; j < 8; j++) {
        int col = head * HDIM + j * 8 + cbm;
        *(uint16_t*)(O8 + (size_t)row0 * DMODEL + col) =
            f2e4m3x2(accO[j][0] * li0, accO[j][1] * li0);
        *(uint16_t*)(O8 + (size_t)(row0 + 8) * DMODEL + col) =
            f2e4m3x2(accO[j][2] * li1, accO[j][3] * li1);
    }
}

// ---------------- misc small kernels ----------------
__global__ void zero_kernel(float* __restrict__ p, int n) {
    int i = blockIdx.x * blockDim.x + threadIdx.x;
    if (i < n) p[i] = 0.f;
}
__global__ void tgt_kernel(const bf16* __restrict__ XR, const float* __restrict__ u_emb,
                           const int* __restrict__ y, float* __restrict__ tgt) {
    int row = blockIdx.x * 4 + (threadIdx.x >> 5);
    int lane = threadIdx.x & 31;
    if (row >= TT) return;
    int t = y[row];
    const bf16* h = XR + (size_t)row * DMODEL;
    const float* u = u_emb + (size_t)t * 512;
    float s = 0.f;
    for (int i = lane * 4; i < 512; i += 128) {
        bf162 h0 = *(const bf162*)(h + i);
        bf162 h1 = *(const bf162*)(h + i + 2);
        float4 uv = *(const float4*)(u + i);
        s += __bfloat162float(h0.x) * uv.x + __bfloat162float(h0.y) * uv.y
           + __bfloat162float(h1.x) * uv.z + __bfloat162float(h1.y) * uv.w;
    }
    #pragma unroll
    for (int off = 16; off; off >>= 1) s += __shfl_xor_sync(0xffffffffu, s, off);
    if (lane == 0) tgt[row] = 30.f * tanhf(s * (1.f / 30.f));
}
__global__ void loss_kernel(const float* __restrict__ sumexp, const float* __restrict__ tgt,
                            float* __restrict__ out) {
    float s = 0.f;
    for (int i = threadIdx.x; i < TT; i += 256)
        s += logf(sumexp[i]) - tgt[i];
    float tot = block_sum_256(s);
    if (threadIdx.x == 0) out[0] = tot * (1.f / TT);
}

// ---------------- host orchestration ----------------
static inline void gemm8(const uint8_t* A, int lda, const uint8_t* W,
                         float* Cf, bf16* Ch, float* Csk, int ldc,
                         const float* scale, float* sumexp,
                         int M, int N, int K, int mode) {
    dim3 grid((N + 127) / 128, M / 128);
    gemm_fp8_kernel<<<grid, 256, GEMM_SMEM>>>(A, lda, W, Cf, Ch, Csk, ldc,
                                              scale, sumexp, M, N, K, mode, WSCI);
}
static inline void gemmh(const bf16* A, int lda, const bf16* W,
                         uint8_t* C8, int ldc, int M, int N, int K) {
    dim3 grid((N + 127) / 128, M / 128);
    gemm_bf16_kernel<<<grid, 256, GEMM_SMEM>>>(A, lda, W, C8, ldc, M, N, K);
}

extern "C" void kernel_launch(void* const* d_in, const int* in_sizes, int n_in,
                              void* d_out, int out_size) {
    const int*   ids     = (const int*)d_in[0];
    const int*   y       = (const int*)d_in[1];
    const float* u_emb   = (const float*)d_in[2];
    const float* b_emb   = (const float*)d_in[3];
    const float* Wq      = (const float*)d_in[4];
    const float* Wk      = (const float*)d_in[5];
    const float* Wv      = (const float*)d_in[6];
    const float* Wo      = (const float*)d_in[7];
    const float* qg      = (const float*)d_in[8];
    const float* a_scale = (const float*)d_in[9];
    const float* m_scale = (const float*)d_in[10];
    const float* rm      = (const float*)d_in[11];
    const float* Wf      = (const float*)d_in[12];
    const float* Wo2     = (const float*)d_in[13];
    const float* sw      = (const float*)d_in[14];

    cudaFuncSetAttribute(gemm_bf16_kernel, cudaFuncAttributeMaxDynamicSharedMemorySize, GEMM_SMEM);
    cudaFuncSetAttribute(gemm_fp8_kernel,  cudaFuncAttributeMaxDynamicSharedMemorySize, GEMM_SMEM);

    float *X, *X0, *SK, *COS, *SIN, *SUM, *TGT;
    bf16 *XRh, *QKVh, *Qh, *Kh, *Vh, *WFh;
    uint8_t *XR8, *ATT8, *MH8, *WQKV8, *WO8, *WO28, *UE8;
    cudaGetSymbolAddress((void**)&X,     g_X);
    cudaGetSymbolAddress((void**)&X0,    g_X0);
    cudaGetSymbolAddress((void**)&SK,    g_SK);
    cudaGetSymbolAddress((void**)&COS,   g_COS);
    cudaGetSymbolAddress((void**)&SIN,   g_SIN);
    cudaGetSymbolAddress((void**)&SUM,   g_SUMEXP);
    cudaGetSymbolAddress((void**)&TGT,   g_TGT);
    cudaGetSymbolAddress((void**)&XRh,   g_XRh);
    cudaGetSymbolAddress((void**)&XR8,   g_XR8);
    cudaGetSymbolAddress((void**)&QKVh,  g_QKVh);
    cudaGetSymbolAddress((void**)&ATT8,  g_ATT8);
    cudaGetSymbolAddress((void**)&MH8,   g_MH8);
    cudaGetSymbolAddress((void**)&Qh,    g_Qh);
    cudaGetSymbolAddress((void**)&Kh,    g_Kh);
    cudaGetSymbolAddress((void**)&Vh,    g_Vh);
    cudaGetSymbolAddress((void**)&WQKV8, g_WQKV8);
    cudaGetSymbolAddress((void**)&WO8,   g_WO8);
    cudaGetSymbolAddress((void**)&WFh,   g_WFh);
    cudaGetSymbolAddress((void**)&WO28,  g_WO28);
    cudaGetSymbolAddress((void**)&UE8,   g_UE8);

    rope_table_kernel<<<(SEQ * 32 + 255) / 256, 256>>>(COS, SIN);
    {
        int tot = LNUM * QKVD * (DMODEL / 4);
        pack_qkv_kernel<<<(tot + 255) / 256, 256>>>(Wq, Wk, Wv, (uint32_t*)WQKV8);
        int n1 = LNUM * MLPD * DMODEL / 4;    // Wf -> bf16
        int n2 = LNUM * DMODEL * DMODEL / 4;  // Wo -> fp8
        int n3 = LNUM * MLPD * DMODEL / 4;    // Wo2 -> fp8
        int n4 = VSZ * 512 / 4;               // UE -> fp8
        long totc = (long)n1 + n2 + n3 + n4;
        wconv_kernel<<<(int)((totc + 255) / 256), 256>>>(
            (const float4*)Wf,    (bf162*)WFh,     n1,
            (const float4*)Wo,    (uint32_t*)WO8,  n2,
            (const float4*)Wo2,   (uint32_t*)WO28, n3,
            (const float4*)u_emb, (uint32_t*)UE8,  n4);
    }
    embed_kernel<<<TT, 256>>>(ids, u_emb, b_emb, X, X0);

    auto run_block = [&](int l, const float* skip, const float* swv, float* skstore) {
        mix_rmsn_kernel<<<TT, 256>>>(X, X0, XR8, rm + (size_t)l * 2 * DMODEL, skip, swv);
        gemm8(XR8, DMODEL, WQKV8 + (size_t)l * QKVD * DMODEL,
              nullptr, QKVh, nullptr, QKVD, nullptr, nullptr, TT, QKVD, DMODEL, 0);
        qkrope_kernel<<<TT * (NH + 2 * NKV) / 8, 256>>>(QKVh, Qh, Kh, Vh, COS, SIN,
                                                        qg + (size_t)l * NH);
        flash_mma_kernel<<<dim3(32, 32), 128>>>(Qh, Kh, Vh, ATT8);
        gemm8(ATT8, DMODEL, WO8 + (size_t)l * DMODEL * DMODEL,
              X, nullptr, nullptr, DMODEL, a_scale + (size_t)l * DMODEL, nullptr,
              TT, DMODEL, DMODEL, 1);
        rmsn_kernel<<<TT, 256>>>(X, XRh, nullptr);
        gemmh(XRh, DMODEL, WFh + (size_t)l * MLPD * DMODEL, MH8, MLPD, TT, MLPD, DMODEL);
        gemm8(MH8, MLPD, WO28 + (size_t)l * DMODEL * MLPD,
              X, nullptr, skstore, DMODEL, m_scale + (size_t)l * DMODEL, nullptr,
              TT, DMODEL, MLPD, 1);
    };

    // forward pass; skip stash fused into the Wo2 GEMM epilogue
    for (int i = 0; i < LNUM; i++)
        run_block(i, nullptr, nullptr, SK + (size_t)i * TT * DMODEL);
    // reverse pass with skips
    for (int i = 0; i < LNUM; i++) {
        int j = LNUM - 1 - i;
        run_block(j, SK + (size_t)j * TT * DMODEL, sw + (size_t)i * DMODEL, nullptr);
    }

    // final norm + loss
    rmsn_kernel<<<TT, 256>>>(X, XRh, XR8);
    zero_kernel<<<(TT + 255) / 256, 256>>>(SUM, TT);
    gemm8(XR8, DMODEL, UE8, nullptr, nullptr, nullptr, VSZ,
          nullptr, SUM, TT, VSZ, 512, 3);
    tgt_kernel<<<TT / 4, 128>>>(XRh, u_emb, y, TGT);
    loss_kernel<<<1, 256>>>(SUM, TGT, (float*)d_out);
}